// round 10
// baseline (speedup 1.0000x reference)
#include <cuda_runtime.h>
#include <stdint.h>

#define VGRID   64
#define G3      (VGRID * VGRID * VGRID)       // 262144
#define BMAX    8
#define CCH     96
#define NMAX    (BMAX * 131072)               // 1048576
#define NSEG    (BMAX * G3)                   // 2097152

// All state re-derived every replay. g_cnt must be zero at entry: zero at
// module load; gather re-zeroes it each replay. g_total zeroed by index_kernel
// (runs before alloc_kernel each replay).
__device__ int g_seg[NMAX];
__device__ int g_cnt[NSEG];
__device__ int g_pos[NSEG];      // run starts; becomes ends after scatter
__device__ int g_sorted[NMAX];
__device__ int g_total;

// ---------------------------------------------------------------------------
// K1: per-point segment id + int histogram. Also resets g_total for K2.
// NOTE: *50.0f (not /0.02f) is load-bearing — XLA folds the reference's
// constant division into a multiply; dividing flips floor() at boundaries.
// ---------------------------------------------------------------------------
__global__ void index_kernel(const float* __restrict__ coord,
                             const int*   __restrict__ offset,
                             const int*   __restrict__ resolution,
                             int n, int nb) {
    int p = blockIdx.x * blockDim.x + threadIdx.x;
    if (p == 0) g_total = 0;                   // consumed only by alloc_kernel
    if (p >= n) return;

    int b = 0;
    #pragma unroll
    for (int i = 0; i < BMAX; i++)
        if (i < nb && offset[i] <= p) b++;

    float fx = coord[3 * p + 0];
    float fy = coord[3 * p + 1];
    float fz = coord[3 * p + 2];
    float vx = floorf(fx * 50.0f);
    float vy = floorf(fy * 50.0f);
    float vz = floorf(fz * 50.0f);
    float cr = (float)(resolution[b] + 1);
    float sc = __fdiv_rn(cr, (float)VGRID);
    int gx = (int)floorf(__fdiv_rn(vx, sc));
    int gy = (int)floorf(__fdiv_rn(vy, sc));
    int gz = (int)floorf(__fdiv_rn(vz, sc));
    gx = min(max(gx, 0), VGRID - 1);
    gy = min(max(gy, 0), VGRID - 1);
    gz = min(max(gz, 0), VGRID - 1);

    int sp  = (gz * VGRID + gy) * VGRID + gx;   // output spatial order (z,y,x)
    int seg = b * G3 + sp;
    g_seg[p] = seg;
    atomicAdd(&g_cnt[seg], 1);
}

// ---------------------------------------------------------------------------
// K2: run allocation. Replaces the 3-kernel global scan: each 1024-thread
// block scans its 1024 counts and grabs a contiguous region with ONE global
// atomicAdd. Global run order is execution-order-dependent (harmless: gather
// needs only per-voxel contiguity + contiguity within each 32-voxel group,
// both guaranteed by the in-block ordered scan). 2048 same-address atomics
// ~1us; warp-level allocation would be 65K serialized atomics (~30us).
// ---------------------------------------------------------------------------
__global__ void alloc_kernel() {
    __shared__ int s_wtot[32], s_wbase[32];
    __shared__ int s_gbase;
    int tid  = threadIdx.x;                  // 0..1023
    int lane = tid & 31, w = tid >> 5;
    int v = blockIdx.x * 1024 + tid;

    int k = g_cnt[v];
    int x = k;
    #pragma unroll
    for (int d = 1; d < 32; d <<= 1) {
        int y = __shfl_up_sync(0xffffffffu, x, d);
        if (lane >= d) x += y;
    }
    if (lane == 31) s_wtot[w] = x;
    __syncthreads();
    if (w == 0) {
        int t = s_wtot[lane];
        int y = t;
        #pragma unroll
        for (int d = 1; d < 32; d <<= 1) {
            int z = __shfl_up_sync(0xffffffffu, y, d);
            if (lane >= d) y += z;
        }
        s_wbase[lane] = y - t;
        if (lane == 31) s_gbase = atomicAdd(&g_total, y);
    }
    __syncthreads();
    g_pos[v] = s_gbase + s_wbase[w] + (x - k);
}

// ---------------------------------------------------------------------------
// K3: scatter point ids into contiguous per-voxel runs.
// Mutates g_pos: after this, g_pos[v] == end of run v (start = end - cnt).
// ---------------------------------------------------------------------------
__global__ void scatter_kernel(int n) {
    int p = blockIdx.x * blockDim.x + threadIdx.x;
    if (p >= n) return;
    int seg = g_seg[p];
    int pos = atomicAdd(&g_pos[seg], 1);
    g_sorted[pos] = p;
}

// ---------------------------------------------------------------------------
// K4: gather + mean + transpose + output. One block per 32 consecutive voxels
// (whose sorted runs are contiguous in g_sorted). Run staged to smem with
// coalesced loads; hot loop unrolled x2 (6 LDG.128 in flight per thread).
// STG.128 transposed output. Re-zeroes g_cnt for next replay.
// ---------------------------------------------------------------------------
#define FSTRIDE 97
#define STAGE   128

__global__ void gather_kernel(const float* __restrict__ feat,
                              float* __restrict__ out) {
    __shared__ float tile[32 * FSTRIDE];
    __shared__ int   s_loc[32], s_k[32];
    __shared__ float s_rinv[32];
    __shared__ int   s_pid[STAGE];
    __shared__ int   s_base[2];              // [0]=blockStart, [1]=blockTotal

    int vbase = blockIdx.x * 32;
    int tid   = threadIdx.x;

    if (tid < 32) {
        int v = vbase + tid;
        int k = g_cnt[v];
        int e = g_pos[v];                    // end after scatter
        s_k[tid]    = k;
        s_rinv[tid] = (k > 0) ? __fdiv_rn(1.0f, (float)k) : 0.0f;
        g_cnt[v] = 0;                        // reset for next replay
        int x = k;
        #pragma unroll
        for (int d = 1; d < 32; d <<= 1) {
            int y = __shfl_up_sync(0xffffffffu, x, d);
            if (tid >= d) x += y;
        }
        s_loc[tid] = x - k;
        if (tid == 31) {
            s_base[0] = e - x;               // block run start in g_sorted
            s_base[1] = x;                   // total points in block
        }
    }
    __syncthreads();

    int bstart = s_base[0];
    int btotal = s_base[1];
    for (int i = tid; i < btotal && i < STAGE; i += 256)
        s_pid[i] = g_sorted[bstart + i];
    __syncthreads();

    int r = tid >> 3;                        // local voxel 0..31
    int g = tid & 7;                         // float4 slot 0..7
    int k    = s_k[r];
    int loc  = s_loc[r];
    float ri = s_rinv[r];

    float4 a0 = make_float4(0.f, 0.f, 0.f, 0.f);
    float4 a1 = a0, a2 = a0;

    int i = 0;
    for (; i + 2 <= k; i += 2) {             // unroll x2: 6 loads in flight
        int i0 = loc + i, i1 = loc + i + 1;
        int pidA = (i0 < STAGE) ? s_pid[i0] : g_sorted[bstart + i0];
        int pidB = (i1 < STAGE) ? s_pid[i1] : g_sorted[bstart + i1];
        const float4* fa = (const float4*)(feat + (size_t)pidA * CCH);
        const float4* fb = (const float4*)(feat + (size_t)pidB * CCH);
        float4 A0 = __ldcs(fa + g), A1 = __ldcs(fa + g + 8), A2 = __ldcs(fa + g + 16);
        float4 B0 = __ldcs(fb + g), B1 = __ldcs(fb + g + 8), B2 = __ldcs(fb + g + 16);
        a0.x += A0.x + B0.x; a0.y += A0.y + B0.y; a0.z += A0.z + B0.z; a0.w += A0.w + B0.w;
        a1.x += A1.x + B1.x; a1.y += A1.y + B1.y; a1.z += A1.z + B1.z; a1.w += A1.w + B1.w;
        a2.x += A2.x + B2.x; a2.y += A2.y + B2.y; a2.z += A2.z + B2.z; a2.w += A2.w + B2.w;
    }
    if (i < k) {
        int i0 = loc + i;
        int pid = (i0 < STAGE) ? s_pid[i0] : g_sorted[bstart + i0];
        const float4* fr = (const float4*)(feat + (size_t)pid * CCH);
        float4 f0 = __ldcs(fr + g), f1 = __ldcs(fr + g + 8), f2 = __ldcs(fr + g + 16);
        a0.x += f0.x; a0.y += f0.y; a0.z += f0.z; a0.w += f0.w;
        a1.x += f1.x; a1.y += f1.y; a1.z += f1.z; a1.w += f1.w;
        a2.x += f2.x; a2.y += f2.y; a2.z += f2.z; a2.w += f2.w;
    }
    a0.x *= ri; a0.y *= ri; a0.z *= ri; a0.w *= ri;
    a1.x *= ri; a1.y *= ri; a1.z *= ri; a1.w *= ri;
    a2.x *= ri; a2.y *= ri; a2.z *= ri; a2.w *= ri;

    int base = r * FSTRIDE + g * 4;
    tile[base +  0] = a0.x; tile[base +  1] = a0.y;
    tile[base +  2] = a0.z; tile[base +  3] = a0.w;
    tile[base + 32] = a1.x; tile[base + 33] = a1.y;
    tile[base + 34] = a1.z; tile[base + 35] = a1.w;
    tile[base + 64] = a2.x; tile[base + 65] = a2.y;
    tile[base + 66] = a2.z; tile[base + 67] = a2.w;
    __syncthreads();

    // Write phase: 768 float4 stores per block, 3 per thread (STG.128).
    int b   = vbase >> 18;                   // / G3
    int sp0 = vbase & (G3 - 1);
    #pragma unroll
    for (int m = 0; m < 3; m++) {
        int idx = tid + 256 * m;
        int c   = idx >> 3;
        int xq  = idx & 7;
        float4 v4;
        v4.x = tile[(4 * xq + 0) * FSTRIDE + c];
        v4.y = tile[(4 * xq + 1) * FSTRIDE + c];
        v4.z = tile[(4 * xq + 2) * FSTRIDE + c];
        v4.w = tile[(4 * xq + 3) * FSTRIDE + c];
        __stcs((float4*)(out + ((size_t)(b * CCH + c)) * G3 + sp0 + 4 * xq), v4);
    }
}

// ---------------------------------------------------------------------------
extern "C" void kernel_launch(void* const* d_in, const int* in_sizes, int n_in,
                              void* d_out, int out_size) {
    const float* coord      = (const float*)d_in[0];
    const float* feat       = (const float*)d_in[1];
    const int*   offset     = (const int*)d_in[2];
    const int*   resolution = (const int*)d_in[3];
    float*       out        = (float*)d_out;

    int n  = in_sizes[0] / 3;
    int nb = in_sizes[2];
    if (nb > BMAX) nb = BMAX;

    index_kernel<<<(n + 255) / 256, 256>>>(coord, offset, resolution, n, nb);
    alloc_kernel<<<NSEG / 1024, 1024>>>();
    scatter_kernel<<<(n + 255) / 256, 256>>>(n);
    gather_kernel<<<NSEG / 32, 256>>>(feat, out);
}

// round 12
// speedup vs baseline: 1.0798x; 1.0798x over previous
#include <cuda_runtime.h>
#include <stdint.h>

#define VGRID   64
#define G3      (VGRID * VGRID * VGRID)       // 262144
#define BMAX    8
#define CCH     96
#define NMAX    (BMAX * 131072)               // 1048576
#define NSEG    (BMAX * G3)                   // 2097152

// All state re-derived every replay. g_cnt must be zero at entry: zero at
// module load; gather re-zeroes it each replay. g_total zeroed by index_kernel
// (runs before alloc_kernel each replay).
__device__ int g_seg[NMAX];
__device__ int g_cnt[NSEG];
__device__ int g_pos[NSEG];      // run starts; becomes ends after scatter
__device__ int g_sorted[NMAX];
__device__ int g_total;

// ---------------------------------------------------------------------------
// K1: per-point segment id + int histogram. Also resets g_total for K2.
// NOTE: *50.0f (not /0.02f) is load-bearing — XLA folds the reference's
// constant division into a multiply; dividing flips floor() at boundaries.
// ---------------------------------------------------------------------------
__global__ void index_kernel(const float* __restrict__ coord,
                             const int*   __restrict__ offset,
                             const int*   __restrict__ resolution,
                             int n, int nb) {
    int p = blockIdx.x * blockDim.x + threadIdx.x;
    if (p == 0) g_total = 0;                   // consumed only by alloc_kernel
    if (p >= n) return;

    int b = 0;
    #pragma unroll
    for (int i = 0; i < BMAX; i++)
        if (i < nb && offset[i] <= p) b++;

    float fx = coord[3 * p + 0];
    float fy = coord[3 * p + 1];
    float fz = coord[3 * p + 2];
    float vx = floorf(fx * 50.0f);
    float vy = floorf(fy * 50.0f);
    float vz = floorf(fz * 50.0f);
    float cr = (float)(resolution[b] + 1);
    float sc = __fdiv_rn(cr, (float)VGRID);
    int gx = (int)floorf(__fdiv_rn(vx, sc));
    int gy = (int)floorf(__fdiv_rn(vy, sc));
    int gz = (int)floorf(__fdiv_rn(vz, sc));
    gx = min(max(gx, 0), VGRID - 1);
    gy = min(max(gy, 0), VGRID - 1);
    gz = min(max(gz, 0), VGRID - 1);

    int sp  = (gz * VGRID + gy) * VGRID + gx;   // output spatial order (z,y,x)
    int seg = b * G3 + sp;
    g_seg[p] = seg;
    atomicAdd(&g_cnt[seg], 1);
}

// ---------------------------------------------------------------------------
// K2: run allocation (replaces 3-kernel global scan). Each 1024-thread block
// scans its 1024 counts in-block and grabs a contiguous region with ONE
// global atomicAdd. Run placement is execution-order-dependent, which is
// harmless: gather needs only per-voxel contiguity + contiguity within each
// 32-voxel group, both guaranteed by the in-block ordered scan.
// ---------------------------------------------------------------------------
__global__ void alloc_kernel() {
    __shared__ int s_wtot[32], s_wbase[32];
    __shared__ int s_gbase;
    int tid  = threadIdx.x;                  // 0..1023
    int lane = tid & 31, w = tid >> 5;
    int v = blockIdx.x * 1024 + tid;

    int k = g_cnt[v];
    int x = k;
    #pragma unroll
    for (int d = 1; d < 32; d <<= 1) {
        int y = __shfl_up_sync(0xffffffffu, x, d);
        if (lane >= d) x += y;
    }
    if (lane == 31) s_wtot[w] = x;
    __syncthreads();
    if (w == 0) {
        int t = s_wtot[lane];
        int y = t;
        #pragma unroll
        for (int d = 1; d < 32; d <<= 1) {
            int z = __shfl_up_sync(0xffffffffu, y, d);
            if (lane >= d) y += z;
        }
        s_wbase[lane] = y - t;
        if (lane == 31) s_gbase = atomicAdd(&g_total, y);
    }
    __syncthreads();
    g_pos[v] = s_gbase + s_wbase[w] + (x - k);
}

// ---------------------------------------------------------------------------
// K3: scatter point ids into contiguous per-voxel runs.
// Mutates g_pos: after this, g_pos[v] == end of run v (start = end - cnt).
// ---------------------------------------------------------------------------
__global__ void scatter_kernel(int n) {
    int p = blockIdx.x * blockDim.x + threadIdx.x;
    if (p >= n) return;
    int seg = g_seg[p];
    int pos = atomicAdd(&g_pos[seg], 1);
    g_sorted[pos] = p;
}

// ---------------------------------------------------------------------------
// K4: gather + mean + transpose + output (R8 form — single-iteration hot
// loop, 3 LDG.128 in flight; the R9 unroll x2 raised regs 42->52 and dropped
// occupancy 59->47%, regressing. Do not re-unroll.). One block per 32
// consecutive voxels; run staged to smem coalesced; STG.128 output stores.
// Re-zeroes g_cnt for next replay.
// ---------------------------------------------------------------------------
#define FSTRIDE 97
#define STAGE   128

__global__ void gather_kernel(const float* __restrict__ feat,
                              float* __restrict__ out) {
    __shared__ float tile[32 * FSTRIDE];
    __shared__ int   s_loc[32], s_k[32];
    __shared__ float s_rinv[32];
    __shared__ int   s_pid[STAGE];
    __shared__ int   s_base[2];              // [0]=blockStart, [1]=blockTotal

    int vbase = blockIdx.x * 32;
    int tid   = threadIdx.x;

    if (tid < 32) {
        int v = vbase + tid;
        int k = g_cnt[v];
        int e = g_pos[v];                    // end after scatter
        s_k[tid]    = k;
        s_rinv[tid] = (k > 0) ? __fdiv_rn(1.0f, (float)k) : 0.0f;
        g_cnt[v] = 0;                        // reset for next replay
        int x = k;
        #pragma unroll
        for (int d = 1; d < 32; d <<= 1) {
            int y = __shfl_up_sync(0xffffffffu, x, d);
            if (tid >= d) x += y;
        }
        s_loc[tid] = x - k;
        if (tid == 31) {
            s_base[0] = e - x;               // block run start in g_sorted
            s_base[1] = x;                   // total points in block
        }
    }
    __syncthreads();

    int bstart = s_base[0];
    int btotal = s_base[1];
    for (int i = tid; i < btotal && i < STAGE; i += 256)
        s_pid[i] = g_sorted[bstart + i];
    __syncthreads();

    int r = tid >> 3;                        // local voxel 0..31
    int g = tid & 7;                         // float4 slot 0..7
    int k    = s_k[r];
    int loc  = s_loc[r];
    float ri = s_rinv[r];

    float4 a0 = make_float4(0.f, 0.f, 0.f, 0.f);
    float4 a1 = a0, a2 = a0;

    if (btotal <= STAGE) {
        // Common case: all pids staged; no per-iteration bounds select.
        for (int i = 0; i < k; i++) {
            int pid = s_pid[loc + i];
            const float4* fr = (const float4*)(feat + (size_t)pid * CCH);
            float4 f0 = __ldcs(fr + g), f1 = __ldcs(fr + g + 8), f2 = __ldcs(fr + g + 16);
            a0.x += f0.x; a0.y += f0.y; a0.z += f0.z; a0.w += f0.w;
            a1.x += f1.x; a1.y += f1.y; a1.z += f1.z; a1.w += f1.w;
            a2.x += f2.x; a2.y += f2.y; a2.z += f2.z; a2.w += f2.w;
        }
    } else {
        for (int i = 0; i < k; i++) {
            int idx = loc + i;
            int pid = (idx < STAGE) ? s_pid[idx] : g_sorted[bstart + idx];
            const float4* fr = (const float4*)(feat + (size_t)pid * CCH);
            float4 f0 = __ldcs(fr + g), f1 = __ldcs(fr + g + 8), f2 = __ldcs(fr + g + 16);
            a0.x += f0.x; a0.y += f0.y; a0.z += f0.z; a0.w += f0.w;
            a1.x += f1.x; a1.y += f1.y; a1.z += f1.z; a1.w += f1.w;
            a2.x += f2.x; a2.y += f2.y; a2.z += f2.z; a2.w += f2.w;
        }
    }
    a0.x *= ri; a0.y *= ri; a0.z *= ri; a0.w *= ri;
    a1.x *= ri; a1.y *= ri; a1.z *= ri; a1.w *= ri;
    a2.x *= ri; a2.y *= ri; a2.z *= ri; a2.w *= ri;

    int base = r * FSTRIDE + g * 4;
    tile[base +  0] = a0.x; tile[base +  1] = a0.y;
    tile[base +  2] = a0.z; tile[base +  3] = a0.w;
    tile[base + 32] = a1.x; tile[base + 33] = a1.y;
    tile[base + 34] = a1.z; tile[base + 35] = a1.w;
    tile[base + 64] = a2.x; tile[base + 65] = a2.y;
    tile[base + 66] = a2.z; tile[base + 67] = a2.w;
    __syncthreads();

    // Write phase: 768 float4 stores per block, 3 per thread (STG.128).
    int b   = vbase >> 18;                   // / G3
    int sp0 = vbase & (G3 - 1);
    #pragma unroll
    for (int m = 0; m < 3; m++) {
        int idx = tid + 256 * m;
        int c   = idx >> 3;
        int xq  = idx & 7;
        float4 v4;
        v4.x = tile[(4 * xq + 0) * FSTRIDE + c];
        v4.y = tile[(4 * xq + 1) * FSTRIDE + c];
        v4.z = tile[(4 * xq + 2) * FSTRIDE + c];
        v4.w = tile[(4 * xq + 3) * FSTRIDE + c];
        __stcs((float4*)(out + ((size_t)(b * CCH + c)) * G3 + sp0 + 4 * xq), v4);
    }
}

// ---------------------------------------------------------------------------
extern "C" void kernel_launch(void* const* d_in, const int* in_sizes, int n_in,
                              void* d_out, int out_size) {
    const float* coord      = (const float*)d_in[0];
    const float* feat       = (const float*)d_in[1];
    const int*   offset     = (const int*)d_in[2];
    const int*   resolution = (const int*)d_in[3];
    float*       out        = (float*)d_out;

    int n  = in_sizes[0] / 3;
    int nb = in_sizes[2];
    if (nb > BMAX) nb = BMAX;

    index_kernel<<<(n + 255) / 256, 256>>>(coord, offset, resolution, n, nb);
    alloc_kernel<<<NSEG / 1024, 1024>>>();
    scatter_kernel<<<(n + 255) / 256, 256>>>(n);
    gather_kernel<<<NSEG / 32, 256>>>(feat, out);
}

// round 13
// speedup vs baseline: 1.1971x; 1.1086x over previous
#include <cuda_runtime.h>
#include <stdint.h>

#define VGRID   64
#define G3      (VGRID * VGRID * VGRID)       // 262144
#define BMAX    8
#define CCH     96
#define NMAX    (BMAX * 131072)               // 1048576
#define NSEG    (BMAX * G3)                   // 2097152

// All state re-derived every replay. g_cnt must be zero at entry: zero at
// module load; gather re-zeroes it each replay. g_total zeroed by index_kernel
// (runs before alloc_kernel each replay).
__device__ int g_seg[NMAX];
__device__ int g_cnt[NSEG];
__device__ int g_pos[NSEG];      // run starts; becomes ends after scatter
__device__ int g_sorted[NMAX];
__device__ int g_total;

// ---------------------------------------------------------------------------
// K1: per-point segment id + int histogram. Also resets g_total for K2.
// NOTE: *50.0f (not /0.02f) is load-bearing — XLA folds the reference's
// constant division into a multiply; dividing flips floor() at boundaries.
// ---------------------------------------------------------------------------
__global__ void index_kernel(const float* __restrict__ coord,
                             const int*   __restrict__ offset,
                             const int*   __restrict__ resolution,
                             int n, int nb) {
    int p = blockIdx.x * blockDim.x + threadIdx.x;
    if (p == 0) g_total = 0;                   // consumed only by alloc_kernel
    if (p >= n) return;

    int b = 0;
    #pragma unroll
    for (int i = 0; i < BMAX; i++)
        if (i < nb && offset[i] <= p) b++;

    float fx = coord[3 * p + 0];
    float fy = coord[3 * p + 1];
    float fz = coord[3 * p + 2];
    float vx = floorf(fx * 50.0f);
    float vy = floorf(fy * 50.0f);
    float vz = floorf(fz * 50.0f);
    float cr = (float)(resolution[b] + 1);
    float sc = __fdiv_rn(cr, (float)VGRID);
    int gx = (int)floorf(__fdiv_rn(vx, sc));
    int gy = (int)floorf(__fdiv_rn(vy, sc));
    int gz = (int)floorf(__fdiv_rn(vz, sc));
    gx = min(max(gx, 0), VGRID - 1);
    gy = min(max(gy, 0), VGRID - 1);
    gz = min(max(gz, 0), VGRID - 1);

    int sp  = (gz * VGRID + gy) * VGRID + gx;   // output spatial order (z,y,x)
    int seg = b * G3 + sp;
    g_seg[p] = seg;
    atomicAdd(&g_cnt[seg], 1);
}

// ---------------------------------------------------------------------------
// K2: run allocation (replaces 3-kernel global scan). Each 1024-thread block
// scans its 1024 counts in-block and grabs a contiguous region with ONE
// global atomicAdd. Run placement is execution-order-dependent, which is
// harmless: gather needs only per-voxel contiguity + contiguity within each
// 32-voxel group, both guaranteed by the in-block ordered scan.
// ---------------------------------------------------------------------------
__global__ void alloc_kernel() {
    __shared__ int s_wtot[32], s_wbase[32];
    __shared__ int s_gbase;
    int tid  = threadIdx.x;                  // 0..1023
    int lane = tid & 31, w = tid >> 5;
    int v = blockIdx.x * 1024 + tid;

    int k = g_cnt[v];
    int x = k;
    #pragma unroll
    for (int d = 1; d < 32; d <<= 1) {
        int y = __shfl_up_sync(0xffffffffu, x, d);
        if (lane >= d) x += y;
    }
    if (lane == 31) s_wtot[w] = x;
    __syncthreads();
    if (w == 0) {
        int t = s_wtot[lane];
        int y = t;
        #pragma unroll
        for (int d = 1; d < 32; d <<= 1) {
            int z = __shfl_up_sync(0xffffffffu, y, d);
            if (lane >= d) y += z;
        }
        s_wbase[lane] = y - t;
        if (lane == 31) s_gbase = atomicAdd(&g_total, y);
    }
    __syncthreads();
    g_pos[v] = s_gbase + s_wbase[w] + (x - k);
}

// ---------------------------------------------------------------------------
// K3: scatter point ids into contiguous per-voxel runs.
// Mutates g_pos: after this, g_pos[v] == end of run v (start = end - cnt).
// ---------------------------------------------------------------------------
__global__ void scatter_kernel(int n) {
    int p = blockIdx.x * blockDim.x + threadIdx.x;
    if (p >= n) return;
    int seg = g_seg[p];
    int pos = atomicAdd(&g_pos[seg], 1);
    g_sorted[pos] = p;
}

// ---------------------------------------------------------------------------
// K4: gather + mean + transpose + output. One block per 32 consecutive
// voxels; run staged to smem coalesced; single-iteration hot loop (R9's
// unroll x2 regressed: regs 42->52, occ 59->47 — do not re-unroll).
// __launch_bounds__(256, 6): cap regs ~40 so 6 blocks/SM fit -> occ ~75%
// (at 44 regs only 5 fit, the R11 59%-occupancy ceiling). STG.128 output.
// Re-zeroes g_cnt for next replay.
// ---------------------------------------------------------------------------
#define FSTRIDE 97
#define STAGE   128

__global__ void __launch_bounds__(256, 6)
gather_kernel(const float* __restrict__ feat, float* __restrict__ out) {
    __shared__ float tile[32 * FSTRIDE];
    __shared__ int   s_loc[32], s_k[32];
    __shared__ float s_rinv[32];
    __shared__ int   s_pid[STAGE];
    __shared__ int   s_base[2];              // [0]=blockStart, [1]=blockTotal

    int vbase = blockIdx.x * 32;
    int tid   = threadIdx.x;

    if (tid < 32) {
        int v = vbase + tid;
        int k = g_cnt[v];
        int e = g_pos[v];                    // end after scatter
        s_k[tid]    = k;
        s_rinv[tid] = (k > 0) ? __fdiv_rn(1.0f, (float)k) : 0.0f;
        g_cnt[v] = 0;                        // reset for next replay
        int x = k;
        #pragma unroll
        for (int d = 1; d < 32; d <<= 1) {
            int y = __shfl_up_sync(0xffffffffu, x, d);
            if (tid >= d) x += y;
        }
        s_loc[tid] = x - k;
        if (tid == 31) {
            s_base[0] = e - x;               // block run start in g_sorted
            s_base[1] = x;                   // total points in block
        }
    }
    __syncthreads();

    int bstart = s_base[0];
    int bcap   = min(s_base[1], STAGE);
    for (int i = tid; i < bcap; i += 256)
        s_pid[i] = g_sorted[bstart + i];
    __syncthreads();

    int r = tid >> 3;                        // local voxel 0..31
    int g = tid & 7;                         // float4 slot 0..7
    int k    = s_k[r];
    int loc  = s_loc[r];
    float ri = s_rinv[r];

    float4 a0 = make_float4(0.f, 0.f, 0.f, 0.f);
    float4 a1 = a0, a2 = a0;

    for (int i = 0; i < k; i++) {
        int idx = loc + i;
        int pid = (idx < STAGE) ? s_pid[idx] : g_sorted[bstart + idx];
        const float4* fr = (const float4*)(feat + (size_t)pid * CCH);
        float4 f0 = __ldcs(fr + g), f1 = __ldcs(fr + g + 8), f2 = __ldcs(fr + g + 16);
        a0.x += f0.x; a0.y += f0.y; a0.z += f0.z; a0.w += f0.w;
        a1.x += f1.x; a1.y += f1.y; a1.z += f1.z; a1.w += f1.w;
        a2.x += f2.x; a2.y += f2.y; a2.z += f2.z; a2.w += f2.w;
    }
    a0.x *= ri; a0.y *= ri; a0.z *= ri; a0.w *= ri;
    a1.x *= ri; a1.y *= ri; a1.z *= ri; a1.w *= ri;
    a2.x *= ri; a2.y *= ri; a2.z *= ri; a2.w *= ri;

    int base = r * FSTRIDE + g * 4;
    tile[base +  0] = a0.x; tile[base +  1] = a0.y;
    tile[base +  2] = a0.z; tile[base +  3] = a0.w;
    tile[base + 32] = a1.x; tile[base + 33] = a1.y;
    tile[base + 34] = a1.z; tile[base + 35] = a1.w;
    tile[base + 64] = a2.x; tile[base + 65] = a2.y;
    tile[base + 66] = a2.z; tile[base + 67] = a2.w;
    __syncthreads();

    // Write phase: 768 float4 stores per block, 3 per thread (STG.128).
    int b   = vbase >> 18;                   // / G3
    int sp0 = vbase & (G3 - 1);
    #pragma unroll
    for (int m = 0; m < 3; m++) {
        int idx = tid + 256 * m;
        int c   = idx >> 3;
        int xq  = idx & 7;
        float4 v4;
        v4.x = tile[(4 * xq + 0) * FSTRIDE + c];
        v4.y = tile[(4 * xq + 1) * FSTRIDE + c];
        v4.z = tile[(4 * xq + 2) * FSTRIDE + c];
        v4.w = tile[(4 * xq + 3) * FSTRIDE + c];
        __stcs((float4*)(out + ((size_t)(b * CCH + c)) * G3 + sp0 + 4 * xq), v4);
    }
}

// ---------------------------------------------------------------------------
extern "C" void kernel_launch(void* const* d_in, const int* in_sizes, int n_in,
                              void* d_out, int out_size) {
    const float* coord      = (const float*)d_in[0];
    const float* feat       = (const float*)d_in[1];
    const int*   offset     = (const int*)d_in[2];
    const int*   resolution = (const int*)d_in[3];
    float*       out        = (float*)d_out;

    int n  = in_sizes[0] / 3;
    int nb = in_sizes[2];
    if (nb > BMAX) nb = BMAX;

    index_kernel<<<(n + 255) / 256, 256>>>(coord, offset, resolution, n, nb);
    alloc_kernel<<<NSEG / 1024, 1024>>>();
    scatter_kernel<<<(n + 255) / 256, 256>>>(n);
    gather_kernel<<<NSEG / 32, 256>>>(feat, out);
}

// round 14
// speedup vs baseline: 1.2696x; 1.0606x over previous
#include <cuda_runtime.h>
#include <stdint.h>

#define VGRID   64
#define G3      (VGRID * VGRID * VGRID)       // 262144
#define BMAX    8
#define CCH     96
#define NMAX    (BMAX * 131072)               // 1048576
#define NSEG    (BMAX * G3)                   // 2097152

// All state re-derived every replay. g_cnt must be zero at entry: zero at
// module load; gather re-zeroes it each replay. g_total zeroed by index_kernel
// (runs before alloc_kernel each replay).
__device__ int g_seg[NMAX];
__device__ int g_cnt[NSEG];
__device__ int g_pos[NSEG];      // run starts; becomes ends after scatter
__device__ int g_sorted[NMAX];
__device__ int g_total;

// ---------------------------------------------------------------------------
// K1: per-point segment id + int histogram. Also resets g_total for K2.
// NOTE: *50.0f (not /0.02f) is load-bearing — XLA folds the reference's
// constant division into a multiply; dividing flips floor() at boundaries.
// ---------------------------------------------------------------------------
__global__ void index_kernel(const float* __restrict__ coord,
                             const int*   __restrict__ offset,
                             const int*   __restrict__ resolution,
                             int n, int nb) {
    int p = blockIdx.x * blockDim.x + threadIdx.x;
    if (p == 0) g_total = 0;                   // consumed only by alloc_kernel
    if (p >= n) return;

    int b = 0;
    #pragma unroll
    for (int i = 0; i < BMAX; i++)
        if (i < nb && offset[i] <= p) b++;

    float fx = coord[3 * p + 0];
    float fy = coord[3 * p + 1];
    float fz = coord[3 * p + 2];
    float vx = floorf(fx * 50.0f);
    float vy = floorf(fy * 50.0f);
    float vz = floorf(fz * 50.0f);
    float cr = (float)(resolution[b] + 1);
    float sc = __fdiv_rn(cr, (float)VGRID);
    int gx = (int)floorf(__fdiv_rn(vx, sc));
    int gy = (int)floorf(__fdiv_rn(vy, sc));
    int gz = (int)floorf(__fdiv_rn(vz, sc));
    gx = min(max(gx, 0), VGRID - 1);
    gy = min(max(gy, 0), VGRID - 1);
    gz = min(max(gz, 0), VGRID - 1);

    int sp  = (gz * VGRID + gy) * VGRID + gx;   // output spatial order (z,y,x)
    int seg = b * G3 + sp;
    g_seg[p] = seg;
    atomicAdd(&g_cnt[seg], 1);
}

// ---------------------------------------------------------------------------
// K2: run allocation (replaces 3-kernel global scan). Each 1024-thread block
// scans its 1024 counts in-block and grabs a contiguous region with ONE
// global atomicAdd. Run placement is execution-order-dependent, which is
// harmless: gather needs only per-voxel contiguity + contiguity within each
// 32-voxel group, both guaranteed by the in-block ordered scan.
// ---------------------------------------------------------------------------
__global__ void alloc_kernel() {
    __shared__ int s_wtot[32], s_wbase[32];
    __shared__ int s_gbase;
    int tid  = threadIdx.x;                  // 0..1023
    int lane = tid & 31, w = tid >> 5;
    int v = blockIdx.x * 1024 + tid;

    int k = g_cnt[v];
    int x = k;
    #pragma unroll
    for (int d = 1; d < 32; d <<= 1) {
        int y = __shfl_up_sync(0xffffffffu, x, d);
        if (lane >= d) x += y;
    }
    if (lane == 31) s_wtot[w] = x;
    __syncthreads();
    if (w == 0) {
        int t = s_wtot[lane];
        int y = t;
        #pragma unroll
        for (int d = 1; d < 32; d <<= 1) {
            int z = __shfl_up_sync(0xffffffffu, y, d);
            if (lane >= d) y += z;
        }
        s_wbase[lane] = y - t;
        if (lane == 31) s_gbase = atomicAdd(&g_total, y);
    }
    __syncthreads();
    g_pos[v] = s_gbase + s_wbase[w] + (x - k);
}

// ---------------------------------------------------------------------------
// K3: scatter point ids into contiguous per-voxel runs.
// Mutates g_pos: after this, g_pos[v] == end of run v (start = end - cnt).
// ---------------------------------------------------------------------------
__global__ void scatter_kernel(int n) {
    int p = blockIdx.x * blockDim.x + threadIdx.x;
    if (p >= n) return;
    int seg = g_seg[p];
    int pos = atomicAdd(&g_pos[seg], 1);
    g_sorted[pos] = p;
}

// ---------------------------------------------------------------------------
// K4: gather + transpose + output. One block per 32 consecutive voxels.
// __launch_bounds__(256, 7): target 36 regs -> 7 blocks/SM (occ ~85%; R12's
// 6-block/40-reg config measured occ 72.8%). The 1/k normalization is moved
// to the write phase (s_rinv lookup per output element) to shave hot-loop
// regs/FMULs. Single-iteration hot loop (R9 unroll x2 regressed; do not
// re-unroll). STG.128 output. Re-zeroes g_cnt for next replay.
// ---------------------------------------------------------------------------
#define FSTRIDE 97
#define STAGE   128

__global__ void __launch_bounds__(256, 7)
gather_kernel(const float* __restrict__ feat, float* __restrict__ out) {
    __shared__ float tile[32 * FSTRIDE];
    __shared__ int   s_loc[32], s_k[32];
    __shared__ float s_rinv[32];
    __shared__ int   s_pid[STAGE];
    __shared__ int   s_base[2];              // [0]=blockStart, [1]=blockTotal

    int vbase = blockIdx.x * 32;
    int tid   = threadIdx.x;

    if (tid < 32) {
        int v = vbase + tid;
        int k = g_cnt[v];
        int e = g_pos[v];                    // end after scatter
        s_k[tid]    = k;
        s_rinv[tid] = (k > 0) ? __fdiv_rn(1.0f, (float)k) : 0.0f;
        g_cnt[v] = 0;                        // reset for next replay
        int x = k;
        #pragma unroll
        for (int d = 1; d < 32; d <<= 1) {
            int y = __shfl_up_sync(0xffffffffu, x, d);
            if (tid >= d) x += y;
        }
        s_loc[tid] = x - k;
        if (tid == 31) {
            s_base[0] = e - x;               // block run start in g_sorted
            s_base[1] = x;                   // total points in block
        }
    }
    __syncthreads();

    int bstart = s_base[0];
    int bcap   = min(s_base[1], STAGE);
    for (int i = tid; i < bcap; i += 256)
        s_pid[i] = g_sorted[bstart + i];
    __syncthreads();

    int r = tid >> 3;                        // local voxel 0..31
    int g = tid & 7;                         // float4 slot 0..7
    int k   = s_k[r];
    int loc = s_loc[r];

    float4 a0 = make_float4(0.f, 0.f, 0.f, 0.f);
    float4 a1 = a0, a2 = a0;

    for (int i = 0; i < k; i++) {
        int idx = loc + i;
        int pid = (idx < STAGE) ? s_pid[idx] : g_sorted[bstart + idx];
        const float4* fr = (const float4*)(feat + (size_t)pid * CCH);
        float4 f0 = __ldcs(fr + g), f1 = __ldcs(fr + g + 8), f2 = __ldcs(fr + g + 16);
        a0.x += f0.x; a0.y += f0.y; a0.z += f0.z; a0.w += f0.w;
        a1.x += f1.x; a1.y += f1.y; a1.z += f1.z; a1.w += f1.w;
        a2.x += f2.x; a2.y += f2.y; a2.z += f2.z; a2.w += f2.w;
    }

    int base = r * FSTRIDE + g * 4;
    tile[base +  0] = a0.x; tile[base +  1] = a0.y;
    tile[base +  2] = a0.z; tile[base +  3] = a0.w;
    tile[base + 32] = a1.x; tile[base + 33] = a1.y;
    tile[base + 34] = a1.z; tile[base + 35] = a1.w;
    tile[base + 64] = a2.x; tile[base + 65] = a2.y;
    tile[base + 66] = a2.z; tile[base + 67] = a2.w;
    __syncthreads();

    // Write phase: 768 float4 stores per block, 3 per thread (STG.128).
    // Normalization applied here: element j of the quad belongs to voxel
    // 4*xq+j -> multiply by s_rinv[4*xq+j].
    int b   = vbase >> 18;                   // / G3
    int sp0 = vbase & (G3 - 1);
    #pragma unroll
    for (int m = 0; m < 3; m++) {
        int idx = tid + 256 * m;
        int c   = idx >> 3;
        int xq  = idx & 7;
        float4 v4;
        v4.x = tile[(4 * xq + 0) * FSTRIDE + c] * s_rinv[4 * xq + 0];
        v4.y = tile[(4 * xq + 1) * FSTRIDE + c] * s_rinv[4 * xq + 1];
        v4.z = tile[(4 * xq + 2) * FSTRIDE + c] * s_rinv[4 * xq + 2];
        v4.w = tile[(4 * xq + 3) * FSTRIDE + c] * s_rinv[4 * xq + 3];
        __stcs((float4*)(out + ((size_t)(b * CCH + c)) * G3 + sp0 + 4 * xq), v4);
    }
}

// ---------------------------------------------------------------------------
extern "C" void kernel_launch(void* const* d_in, const int* in_sizes, int n_in,
                              void* d_out, int out_size) {
    const float* coord      = (const float*)d_in[0];
    const float* feat       = (const float*)d_in[1];
    const int*   offset     = (const int*)d_in[2];
    const int*   resolution = (const int*)d_in[3];
    float*       out        = (float*)d_out;

    int n  = in_sizes[0] / 3;
    int nb = in_sizes[2];
    if (nb > BMAX) nb = BMAX;

    index_kernel<<<(n + 255) / 256, 256>>>(coord, offset, resolution, n, nb);
    alloc_kernel<<<NSEG / 1024, 1024>>>();
    scatter_kernel<<<(n + 255) / 256, 256>>>(n);
    gather_kernel<<<NSEG / 32, 256>>>(feat, out);
}

// round 15
// speedup vs baseline: 1.2914x; 1.0172x over previous
#include <cuda_runtime.h>
#include <stdint.h>

#define VGRID   64
#define G3      (VGRID * VGRID * VGRID)       // 262144
#define BMAX    8
#define CCH     96
#define NMAX    (BMAX * 131072)               // 1048576
#define NSEG    (BMAX * G3)                   // 2097152

// All state re-derived every replay. g_cnt must be zero at entry: zero at
// module load; gather re-zeroes it each replay. g_total zeroed by index_kernel
// (runs before alloc_kernel each replay).
__device__ int g_seg[NMAX];
__device__ int g_cnt[NSEG];
__device__ int g_pos[NSEG];      // run starts; becomes ends after scatter
__device__ int g_sorted[NMAX];
__device__ int g_total;

// ---------------------------------------------------------------------------
// K1: per-point segment id + int histogram. Also resets g_total for K2.
// NOTE: *50.0f (not /0.02f) is load-bearing — XLA folds the reference's
// constant division into a multiply; dividing flips floor() at boundaries.
// ---------------------------------------------------------------------------
__global__ void index_kernel(const float* __restrict__ coord,
                             const int*   __restrict__ offset,
                             const int*   __restrict__ resolution,
                             int n, int nb) {
    int p = blockIdx.x * blockDim.x + threadIdx.x;
    if (p == 0) g_total = 0;                   // consumed only by alloc_kernel
    if (p >= n) return;

    int b = 0;
    #pragma unroll
    for (int i = 0; i < BMAX; i++)
        if (i < nb && offset[i] <= p) b++;

    float fx = coord[3 * p + 0];
    float fy = coord[3 * p + 1];
    float fz = coord[3 * p + 2];
    float vx = floorf(fx * 50.0f);
    float vy = floorf(fy * 50.0f);
    float vz = floorf(fz * 50.0f);
    float cr = (float)(resolution[b] + 1);
    float sc = __fdiv_rn(cr, (float)VGRID);
    int gx = (int)floorf(__fdiv_rn(vx, sc));
    int gy = (int)floorf(__fdiv_rn(vy, sc));
    int gz = (int)floorf(__fdiv_rn(vz, sc));
    gx = min(max(gx, 0), VGRID - 1);
    gy = min(max(gy, 0), VGRID - 1);
    gz = min(max(gz, 0), VGRID - 1);

    int sp  = (gz * VGRID + gy) * VGRID + gx;   // output spatial order (z,y,x)
    int seg = b * G3 + sp;
    g_seg[p] = seg;
    atomicAdd(&g_cnt[seg], 1);
}

// ---------------------------------------------------------------------------
// K2: run allocation (replaces 3-kernel global scan). Each 1024-thread block
// scans its 1024 counts in-block and grabs a contiguous region with ONE
// global atomicAdd. Run placement is execution-order-dependent, which is
// harmless: gather needs only per-voxel contiguity + contiguity within each
// 32-voxel group, both guaranteed by the in-block ordered scan.
// ---------------------------------------------------------------------------
__global__ void alloc_kernel() {
    __shared__ int s_wtot[32], s_wbase[32];
    __shared__ int s_gbase;
    int tid  = threadIdx.x;                  // 0..1023
    int lane = tid & 31, w = tid >> 5;
    int v = blockIdx.x * 1024 + tid;

    int k = g_cnt[v];
    int x = k;
    #pragma unroll
    for (int d = 1; d < 32; d <<= 1) {
        int y = __shfl_up_sync(0xffffffffu, x, d);
        if (lane >= d) x += y;
    }
    if (lane == 31) s_wtot[w] = x;
    __syncthreads();
    if (w == 0) {
        int t = s_wtot[lane];
        int y = t;
        #pragma unroll
        for (int d = 1; d < 32; d <<= 1) {
            int z = __shfl_up_sync(0xffffffffu, y, d);
            if (lane >= d) y += z;
        }
        s_wbase[lane] = y - t;
        if (lane == 31) s_gbase = atomicAdd(&g_total, y);
    }
    __syncthreads();
    g_pos[v] = s_gbase + s_wbase[w] + (x - k);
}

// ---------------------------------------------------------------------------
// K3: scatter point ids into contiguous per-voxel runs.
// Mutates g_pos: after this, g_pos[v] == end of run v (start = end - cnt).
// ---------------------------------------------------------------------------
__global__ void scatter_kernel(int n) {
    int p = blockIdx.x * blockDim.x + threadIdx.x;
    if (p >= n) return;
    int seg = g_seg[p];
    int pos = atomicAdd(&g_pos[seg], 1);
    g_sorted[pos] = p;
}

// ---------------------------------------------------------------------------
// K4: gather + transpose + output. One block per 32 consecutive voxels.
// __launch_bounds__(256, 7) (R13: 32 regs, occ 96.5%). After staging the pid
// list, ALL of the block's feat lines are L2-prefetched in one parallel wave
// (rows are 384B = exactly 3 x 128B lines, line-aligned since 384 = 3*128);
// the hot loop's LDGs then hit L2 or merge with in-flight fetches instead of
// paying serial DRAM latency. Normalization stays in the write phase.
// Single-iteration hot loop (R9 unroll x2 regressed; do not re-unroll).
// STG.128 output. Re-zeroes g_cnt for next replay.
// ---------------------------------------------------------------------------
#define FSTRIDE 97
#define STAGE   128

__global__ void __launch_bounds__(256, 7)
gather_kernel(const float* __restrict__ feat, float* __restrict__ out) {
    __shared__ float tile[32 * FSTRIDE];
    __shared__ int   s_loc[32], s_k[32];
    __shared__ float s_rinv[32];
    __shared__ int   s_pid[STAGE];
    __shared__ int   s_base[2];              // [0]=blockStart, [1]=blockTotal

    int vbase = blockIdx.x * 32;
    int tid   = threadIdx.x;

    if (tid < 32) {
        int v = vbase + tid;
        int k = g_cnt[v];
        int e = g_pos[v];                    // end after scatter
        s_k[tid]    = k;
        s_rinv[tid] = (k > 0) ? __fdiv_rn(1.0f, (float)k) : 0.0f;
        g_cnt[v] = 0;                        // reset for next replay
        int x = k;
        #pragma unroll
        for (int d = 1; d < 32; d <<= 1) {
            int y = __shfl_up_sync(0xffffffffu, x, d);
            if (tid >= d) x += y;
        }
        s_loc[tid] = x - k;
        if (tid == 31) {
            s_base[0] = e - x;               // block run start in g_sorted
            s_base[1] = x;                   // total points in block
        }
    }
    __syncthreads();

    int bstart = s_base[0];
    int bcap   = min(s_base[1], STAGE);
    for (int i = tid; i < bcap; i += 256)
        s_pid[i] = g_sorted[bstart + i];
    __syncthreads();

    // Cooperative L2 prefetch of every feat line this block will read.
    // bcap*3 lines (~48 typical): one fire-and-forget prefetch per thread.
    {
        int nlines = bcap * 3;
        for (int j = tid; j < nlines; j += 256) {
            int pid = s_pid[j / 3];
            const char* pl = (const char*)(feat + (size_t)pid * CCH)
                             + (j % 3) * 128;
            asm volatile("prefetch.global.L2 [%0];" :: "l"(pl));
        }
    }

    int r = tid >> 3;                        // local voxel 0..31
    int g = tid & 7;                         // float4 slot 0..7
    int k   = s_k[r];
    int loc = s_loc[r];

    float4 a0 = make_float4(0.f, 0.f, 0.f, 0.f);
    float4 a1 = a0, a2 = a0;

    for (int i = 0; i < k; i++) {
        int idx = loc + i;
        int pid = (idx < STAGE) ? s_pid[idx] : g_sorted[bstart + idx];
        const float4* fr = (const float4*)(feat + (size_t)pid * CCH);
        float4 f0 = __ldcs(fr + g), f1 = __ldcs(fr + g + 8), f2 = __ldcs(fr + g + 16);
        a0.x += f0.x; a0.y += f0.y; a0.z += f0.z; a0.w += f0.w;
        a1.x += f1.x; a1.y += f1.y; a1.z += f1.z; a1.w += f1.w;
        a2.x += f2.x; a2.y += f2.y; a2.z += f2.z; a2.w += f2.w;
    }

    int base = r * FSTRIDE + g * 4;
    tile[base +  0] = a0.x; tile[base +  1] = a0.y;
    tile[base +  2] = a0.z; tile[base +  3] = a0.w;
    tile[base + 32] = a1.x; tile[base + 33] = a1.y;
    tile[base + 34] = a1.z; tile[base + 35] = a1.w;
    tile[base + 64] = a2.x; tile[base + 65] = a2.y;
    tile[base + 66] = a2.z; tile[base + 67] = a2.w;
    __syncthreads();

    // Write phase: 768 float4 stores per block, 3 per thread (STG.128).
    // Normalization applied here: element j of the quad belongs to voxel
    // 4*xq+j -> multiply by s_rinv[4*xq+j].
    int b   = vbase >> 18;                   // / G3
    int sp0 = vbase & (G3 - 1);
    #pragma unroll
    for (int m = 0; m < 3; m++) {
        int idx = tid + 256 * m;
        int c   = idx >> 3;
        int xq  = idx & 7;
        float4 v4;
        v4.x = tile[(4 * xq + 0) * FSTRIDE + c] * s_rinv[4 * xq + 0];
        v4.y = tile[(4 * xq + 1) * FSTRIDE + c] * s_rinv[4 * xq + 1];
        v4.z = tile[(4 * xq + 2) * FSTRIDE + c] * s_rinv[4 * xq + 2];
        v4.w = tile[(4 * xq + 3) * FSTRIDE + c] * s_rinv[4 * xq + 3];
        __stcs((float4*)(out + ((size_t)(b * CCH + c)) * G3 + sp0 + 4 * xq), v4);
    }
}

// ---------------------------------------------------------------------------
extern "C" void kernel_launch(void* const* d_in, const int* in_sizes, int n_in,
                              void* d_out, int out_size) {
    const float* coord      = (const float*)d_in[0];
    const float* feat       = (const float*)d_in[1];
    const int*   offset     = (const int*)d_in[2];
    const int*   resolution = (const int*)d_in[3];
    float*       out        = (float*)d_out;

    int n  = in_sizes[0] / 3;
    int nb = in_sizes[2];
    if (nb > BMAX) nb = BMAX;

    index_kernel<<<(n + 255) / 256, 256>>>(coord, offset, resolution, n, nb);
    alloc_kernel<<<NSEG / 1024, 1024>>>();
    scatter_kernel<<<(n + 255) / 256, 256>>>(n);
    gather_kernel<<<NSEG / 32, 256>>>(feat, out);
}